// round 16
// baseline (speedup 1.0000x reference)
#include <cuda_runtime.h>
#include <cuda_fp16.h>
#include <cstdint>

// Shapes (fixed)
#define Bc   2
#define Sc   2048
#define Hc   32
#define KVHc 8
#define Dc   128
#define NUM_SLOTS 8192

#define BQ 128
#define BK 64
#define NTHREADS 128            // 4 warps; each warp owns 32 query rows
#define QTILES (Sc/BQ)          // 16
#define NATT   (QTILES*Hc*Bc)   // 1024 attention tiles
#define WCTAS  256              // KV-writer tiles
#define NTILES (NATT + WCTAS)   // 1280 total (writers at t%5==2)
#define NPERS  296              // persistent CTAs = 2 x 148 SMs

#define OUT_ELEMS (Bc*Sc*Hc*Dc)
#define KV_ELEMS  (NUM_SLOTS*2*KVHc*Dc)
#define KN (Bc*Sc*KVHc*Dc)      // 4,194,304

// softmax scale * log2(e)  (applied to Q at staging)
#define SCALE2 ((float)(0.08838834764831845 * 1.4426950408889634))
#define ONES2  0x3C003C00u      // half2(1.0, 1.0)

// SMEM word (uint32) layout; row stride 68 words = 272B (272 mod 128 = 16 ->
// ldmatrix 8-row fetches hit distinct 16B chunks: conflict-free)
#define QKSTR 68
#define ROWB  (QKSTR*4)
#define SM_Qw 0                       // 128 rows: Q tile
#define SM_S0 (128*QKSTR)             // stage 0: K(64) + V(64) rows
#define SM_S1 (SM_S0 + 128*QKSTR)     // stage 1
#define STAGEB (128*QKSTR*4)          // 34,816 B per stage
#define SM_WORDS (SM_S1 + 128*QKSTR)  // 104,448 B

// fp16 scratch (pre-converted K/V) + inverse slot map + steal counter
__device__ __half k16g[KN];
__device__ __half v16g[KN];
__device__ int inv_map[NUM_SLOTS];
__device__ int tile_ctr;

__device__ __forceinline__ uint32_t h2(float a, float b) {
    __half2 h = __floats2half2_rn(a, b);
    return *(uint32_t*)&h;
}
__device__ __forceinline__ uint32_t exp2_pack(float lo, float hi) {
    uint32_t w;
    asm("cvt.rn.f16x2.f32 %0, %1, %2;" : "=r"(w) : "f"(hi), "f"(lo));
    asm("ex2.approx.f16x2 %0, %0;" : "+r"(w));
    return w;
}
__device__ __forceinline__ uint32_t smem_u32(const void* p) {
    uint32_t a;
    asm("{ .reg .u64 t; cvta.to.shared.u64 t, %1; cvt.u32.u64 %0, t; }" : "=r"(a) : "l"(p));
    return a;
}
__device__ __forceinline__ void cp16(uint32_t dst, const void* src) {
    asm volatile("cp.async.cg.shared.global [%0], [%1], 16;" :: "r"(dst), "l"(src));
}
#define CP_COMMIT() asm volatile("cp.async.commit_group;" ::: "memory")
#define CP_WAIT0()  asm volatile("cp.async.wait_group 0;" ::: "memory")

__device__ __forceinline__ void ldsm4(uint32_t* r, uint32_t addr) {
    asm volatile("ldmatrix.sync.aligned.m8n8.x4.shared.b16 {%0,%1,%2,%3}, [%4];"
                 : "=r"(r[0]), "=r"(r[1]), "=r"(r[2]), "=r"(r[3]) : "r"(addr));
}
__device__ __forceinline__ void ldsm4t(uint32_t* r, uint32_t addr) {
    asm volatile("ldmatrix.sync.aligned.m8n8.x4.trans.shared.b16 {%0,%1,%2,%3}, [%4];"
                 : "=r"(r[0]), "=r"(r[1]), "=r"(r[2]), "=r"(r[3]) : "r"(addr));
}
__device__ __forceinline__ void mma_f16(float* c, uint32_t a0, uint32_t a1, uint32_t a2,
                                        uint32_t a3, uint32_t b0, uint32_t b1) {
    asm volatile("mma.sync.aligned.m16n8k16.row.col.f32.f16.f16.f32 "
                 "{%0,%1,%2,%3}, {%4,%5,%6,%7}, {%8,%9}, {%0,%1,%2,%3};"
                 : "+f"(c[0]), "+f"(c[1]), "+f"(c[2]), "+f"(c[3])
                 : "r"(a0), "r"(a1), "r"(a2), "r"(a3), "r"(b0), "r"(b1));
}

// ---------------- prep: fp32 -> fp16 convert (K/V) + inv_map init ----------------
__global__ void convert_kernel(const float* __restrict__ xk, const float* __restrict__ xv) {
    int i = blockIdx.x * blockDim.x + threadIdx.x;
    if (i < NUM_SLOTS) inv_map[i] = -1;
    if (i < KN / 4) {
        float4 a = ((const float4*)xk)[i];
        *(uint2*)(k16g + 4 * (size_t)i) = make_uint2(h2(a.x, a.y), h2(a.z, a.w));
        float4 b = ((const float4*)xv)[i];
        *(uint2*)(v16g + 4 * (size_t)i) = make_uint2(h2(b.x, b.y), h2(b.z, b.w));
    }
}
__global__ void fill_inv_kernel(const int* __restrict__ sel) {
    int i = blockIdx.x * blockDim.x + threadIdx.x;
    if (i == 0) tile_ctr = 0;          // deterministic steal-counter reset
    if (i < Bc * Sc) inv_map[sel[i]] = i;
}

// ---------------- persistent: fp16 flash attention + KV write-out ----------------
__global__ __launch_bounds__(NTHREADS, 2)
void attn_mma_kernel(const float* __restrict__ xq, const float* __restrict__ kvb,
                     const float* __restrict__ xk, const float* __restrict__ xv,
                     float* __restrict__ out, float* __restrict__ kv_out) {
    extern __shared__ uint32_t smw[];
    __shared__ int s_tile;
    const uint32_t sb = smem_u32(smw);

    const int tid  = threadIdx.x;
    const int lane = tid & 31;
    const int warp = tid >> 5;     // 0..3
    const int g    = lane >> 2;
    const int c    = lane & 3;

    // per-lane constants (tile-independent)
    const uint32_t qa0b = sb + (uint32_t)(warp * 32 + (lane & 15)) * ROWB + ((lane >> 4) & 1) * 16;
    const uint32_t qa1b = qa0b + 16 * ROWB;
    const uint32_t ka0 = sb + SM_S0 * 4
                       + (uint32_t)((lane & 7) + ((lane >> 4) & 1) * 8) * ROWB
                       + ((lane >> 3) & 1) * 16;
    const uint32_t va0 = sb + SM_S0 * 4 + 64 * ROWB
                       + (uint32_t)((lane & 7) + ((lane >> 3) & 1) * 8) * ROWB
                       + ((lane >> 4) & 1) * 16;
    const int sch = tid & 15, sr0 = tid >> 4;
    const uint32_t s_off = (uint32_t)sr0 * ROWB + sch * 16;
    const size_t  g_off = (size_t)sr0 * (KVHc * Dc) + sch * 8;
    const size_t STEP = (size_t)BK * (KVHc * Dc);

    for (;;) {
        if (tid == 0) s_tile = atomicAdd(&tile_ctr, 1);
        __syncthreads();            // broadcast tile; also: all warps done with prior tile's smem
        const int t = s_tile;
        if (t >= NTILES) return;

        // ---- KV-writer tile (every 5th, t%5==2) ----
        if (t % 5 == 2) {
            const int widx = t / 5;
            const int per = KV_ELEMS / 4 / WCTAS;            // 16384 float4
            const size_t base = (size_t)widx * per;
            const int per_slot = 2 * KVHc * Dc / 4;          // 512
            const int per_tok  = KVHc * Dc / 4;              // 256
            for (int j = tid; j < per; j += NTHREADS) {
                size_t i = base + j;
                int slot = (int)(i / per_slot);
                int rem  = (int)(i - (size_t)slot * per_slot);
                int tk = inv_map[slot];
                float4 v;
                if (tk < 0)              v = ((const float4*)kvb)[i];
                else if (rem < per_tok)  v = ((const float4*)xk)[(size_t)tk * per_tok + rem];
                else                     v = ((const float4*)xv)[(size_t)tk * per_tok + rem - per_tok];
                ((float4*)kv_out)[i] = v;
            }
            continue;
        }

        // ---- attention tile: rank -> (qt desc, h, b) ----
        const int r  = t - (t + 2) / 5;
        const int qt = (QTILES - 1) - (r >> 6);
        const int h  = (r & 63) >> 1;
        const int b  = r & 1;
        const int kvh = h >> 2;
        const int q0  = qt * BQ;
        const int wr0 = q0 + warp * 32;
        const int niter = 2 * qt + 2;

        const __half* kg = k16g + ((size_t)(b * Sc) * KVHc + kvh) * Dc + g_off;
        const __half* vg = v16g + ((size_t)(b * Sc) * KVHc + kvh) * Dc + g_off;

        // ---- prologue: issue K/V stage 0 FIRST, then convert+stage Q under it ----
        {
            uint32_t kd = sb + SM_S0 * 4 + s_off;
#pragma unroll
            for (int k = 0; k < 8; ++k) {
                cp16(kd + k * (8 * ROWB), kg + (size_t)k * (8 * KVHc * Dc));
                cp16(kd + 64 * ROWB + k * (8 * ROWB), vg + (size_t)k * (8 * KVHc * Dc));
            }
            CP_COMMIT();
            kg += STEP; vg += STEP;

            const float* qb = xq + ((size_t)(b * Sc + q0) * Hc + h) * Dc;
            for (int idx = tid; idx < 128 * 32; idx += NTHREADS) {
                int c4 = idx & 31, row = idx >> 5;
                float4 v = *(const float4*)(qb + (size_t)row * (Hc * Dc) + c4 * 4);
                *(uint2*)(smw + SM_Qw + row * QKSTR + c4 * 2) =
                    make_uint2(h2(v.x * SCALE2, v.y * SCALE2), h2(v.z * SCALE2, v.w * SCALE2));
            }
        }

        float o[2][16][4];
#pragma unroll
        for (int m = 0; m < 2; ++m)
#pragma unroll
            for (int n = 0; n < 16; ++n) { o[m][n][0] = o[m][n][1] = o[m][n][2] = o[m][n][3] = 0.0f; }
        float lacc[2][4] = {{0.f, 0.f, 0.f, 0.f}, {0.f, 0.f, 0.f, 0.f}};

        for (int it = 0; it < niter; ++it) {
            const int k0 = it * BK;

            CP_WAIT0();
            __syncthreads();

            if (it + 1 < niter) {
                const uint32_t sdst = sb + (((it + 1) & 1) ? SM_S1 : SM_S0) * 4 + s_off;
#pragma unroll
                for (int k = 0; k < 8; ++k) {
                    cp16(sdst + k * (8 * ROWB), kg + (size_t)k * (8 * KVHc * Dc));
                    cp16(sdst + 64 * ROWB + k * (8 * ROWB), vg + (size_t)k * (8 * KVHc * Dc));
                }
                CP_COMMIT();
                kg += STEP; vg += STEP;
            }

            if (k0 > wr0 + 31) continue;   // fully masked for this warp (warp-uniform)

            const uint32_t soff = (it & 1) ? (uint32_t)STAGEB : 0u;
            const uint32_t ka = ka0 + soff;
            const uint32_t va = va0 + soff;

            // ---- S = Q K^T : software-pipelined fragments ----
            float s[2][8][4];
#pragma unroll
            for (int m = 0; m < 2; ++m)
#pragma unroll
                for (int n = 0; n < 8; ++n) { s[m][n][0] = s[m][n][1] = s[m][n][2] = s[m][n][3] = 0.0f; }

            uint32_t kb[2][4], qx[2][4], qy[2][4];
            ldsm4(qx[0], qa0b);
            ldsm4(qy[0], qa1b);
            ldsm4(kb[0], ka);
#pragma unroll
            for (int ks = 0; ks < 8; ++ks) {
                uint32_t* x = qx[ks & 1];
                uint32_t* y = qy[ks & 1];
#pragma unroll
                for (int j = 0; j < 4; ++j) {
                    if (j < 3)            ldsm4(kb[(j + 1) & 1], ka + (j + 1) * (16 * ROWB) + ks * 32);
                    else if (ks < 7)      ldsm4(kb[0],           ka + (ks + 1) * 32);
                    if (j == 1 && ks < 7) ldsm4(qx[(ks + 1) & 1], qa0b + (ks + 1) * 32);
                    if (j == 2 && ks < 7) ldsm4(qy[(ks + 1) & 1], qa1b + (ks + 1) * 32);
                    uint32_t* kc = kb[j & 1];
                    mma_f16(s[0][2 * j],     x[0], x[1], x[2], x[3], kc[0], kc[1]);
                    mma_f16(s[0][2 * j + 1], x[0], x[1], x[2], x[3], kc[2], kc[3]);
                    mma_f16(s[1][2 * j],     y[0], y[1], y[2], y[3], kc[0], kc[1]);
                    mma_f16(s[1][2 * j + 1], y[0], y[1], y[2], y[3], kc[2], kc[3]);
                }
            }

            // ---- softmax: packed half2 exp2 -> A fragments ----
            uint32_t pf[2][4][4];
            const bool domask = (k0 + 63 > wr0);
#pragma unroll
            for (int m = 0; m < 2; ++m) {
                const int qgA = wr0 + 16 * m + g;
                const int qgB = qgA + 8;
#pragma unroll
                for (int n = 0; n < 8; ++n) {
                    float s0 = s[m][n][0], s1 = s[m][n][1], s2 = s[m][n][2], s3 = s[m][n][3];
                    if (domask) {
                        int kg2 = k0 + n * 8 + 2 * c;
                        const float NINF = -__int_as_float(0x7f800000);
                        if (kg2 + 0 > qgA) s0 = NINF;
                        if (kg2 + 1 > qgA) s1 = NINF;
                        if (kg2 + 0 > qgB) s2 = NINF;
                        if (kg2 + 1 > qgB) s3 = NINF;
                    }
                    uint32_t w01 = exp2_pack(s0, s1);
                    uint32_t w23 = exp2_pack(s2, s3);
                    int ks = n >> 1;
                    if (n & 1) { pf[m][ks][2] = w01; pf[m][ks][3] = w23; }
                    else       { pf[m][ks][0] = w01; pf[m][ks][1] = w23; }
                }
            }

            // ---- O += P V ; l += P * ones : software-pipelined V fragments ----
            uint32_t vb[2][4];
            ldsm4t(vb[0], va);
#pragma unroll
            for (int ks = 0; ks < 4; ++ks) {
#pragma unroll
                for (int j = 0; j < 8; ++j) {
                    if (j < 7)       ldsm4t(vb[(j + 1) & 1], va + ks * (16 * ROWB) + (j + 1) * 32);
                    else if (ks < 3) ldsm4t(vb[0],           va + (ks + 1) * (16 * ROWB));
                    if (j == 0) {
                        mma_f16(lacc[0], pf[0][ks][0], pf[0][ks][1], pf[0][ks][2], pf[0][ks][3], ONES2, ONES2);
                        mma_f16(lacc[1], pf[1][ks][0], pf[1][ks][1], pf[1][ks][2], pf[1][ks][3], ONES2, ONES2);
                    }
                    uint32_t* vc = vb[j & 1];
                    mma_f16(o[0][2 * j],     pf[0][ks][0], pf[0][ks][1], pf[0][ks][2], pf[0][ks][3], vc[0], vc[1]);
                    mma_f16(o[0][2 * j + 1], pf[0][ks][0], pf[0][ks][1], pf[0][ks][2], pf[0][ks][3], vc[2], vc[3]);
                    mma_f16(o[1][2 * j],     pf[1][ks][0], pf[1][ks][1], pf[1][ks][2], pf[1][ks][3], vc[0], vc[1]);
                    mma_f16(o[1][2 * j + 1], pf[1][ks][0], pf[1][ks][1], pf[1][ks][2], pf[1][ks][3], vc[2], vc[3]);
                }
            }
        }

        // ---- epilogue (no shuffles: ones-MMA left full row sums in lanes) ----
#pragma unroll
        for (int m = 0; m < 2; ++m) {
            const int qgA = wr0 + 16 * m + g;
            const int qgB = qgA + 8;
            float invA = 1.0f / lacc[m][0];
            float invB = 1.0f / lacc[m][2];
            float* obA = out + ((size_t)(b * Sc + qgA) * Hc + h) * Dc;
            float* obB = out + ((size_t)(b * Sc + qgB) * Hc + h) * Dc;
#pragma unroll
            for (int n = 0; n < 16; ++n) {
                int col = n * 8 + 2 * c;
                *(float2*)(obA + col) = make_float2(o[m][n][0] * invA, o[m][n][1] * invA);
                *(float2*)(obB + col) = make_float2(o[m][n][2] * invB, o[m][n][3] * invB);
            }
        }
    }
}

// ---------------------------------------------------------------------------
extern "C" void kernel_launch(void* const* d_in, const int* in_sizes, int n_in,
                              void* d_out, int out_size) {
    const float* xq  = (const float*)d_in[0];
    const float* xk  = (const float*)d_in[1];
    const float* xv  = (const float*)d_in[2];
    const float* kvb = (const float*)d_in[3];
    const int*   sel = (const int*)d_in[4];

    float* out    = (float*)d_out;
    float* kv_out = out + OUT_ELEMS;

    // 1) convert K/V to fp16 + init inverse map
    convert_kernel<<<(KN / 4 + 255) / 256, 256>>>(xk, xv);
    // 2) fill inverse map + reset steal counter
    fill_inv_kernel<<<(Bc * Sc + 255) / 256, 256>>>(sel);

    // 3) persistent fused attention + KV write (work-stealing)
    const int smem_bytes = SM_WORDS * 4;   // 104,448 B -> 2 CTAs/SM
    cudaFuncSetAttribute(attn_mma_kernel, cudaFuncAttributeMaxDynamicSharedMemorySize, smem_bytes);
    attn_mma_kernel<<<NPERS, NTHREADS, smem_bytes>>>(xq, kvb, xk, xv, out, kv_out);
}

// round 17
// speedup vs baseline: 1.0744x; 1.0744x over previous
#include <cuda_runtime.h>
#include <cuda_fp16.h>
#include <cstdint>

// Shapes (fixed)
#define Bc   2
#define Sc   2048
#define Hc   32
#define KVHc 8
#define Dc   128
#define NUM_SLOTS 8192

#define BQ 128
#define BK 64
#define NTHREADS 128            // 4 warps; each warp owns 32 query rows
#define QTILES (Sc/BQ)          // 16
#define WCTAS  256              // fused KV-writer CTAs

#define OUT_ELEMS (Bc*Sc*Hc*Dc)
#define KV_ELEMS  (NUM_SLOTS*2*KVHc*Dc)
#define KN (Bc*Sc*KVHc*Dc)      // 4,194,304

// softmax scale * log2(e)  (applied to Q at staging)
#define SCALE2 ((float)(0.08838834764831845 * 1.4426950408889634))
#define ONES2  0x3C003C00u      // half2(1.0, 1.0)

// SMEM word (uint32) layout; row stride 68 words = 272B (272 mod 128 = 16 ->
// ldmatrix 8-row fetches hit distinct 16B chunks: conflict-free)
#define QKSTR 68
#define ROWB  (QKSTR*4)
#define SM_Qw 0                       // 128 rows: Q tile
#define SM_S0 (128*QKSTR)             // stage 0: K(64) + V(64) rows
#define SM_S1 (SM_S0 + 128*QKSTR)     // stage 1
#define STAGEB (128*QKSTR*4)          // 34,816 B per stage
#define SM_WORDS (SM_S1 + 128*QKSTR)  // 104,448 B

// fp16 scratch (pre-converted K/V) + inverse slot map
__device__ __half k16g[KN];
__device__ __half v16g[KN];
__device__ int inv_map[NUM_SLOTS];

__device__ __forceinline__ uint32_t h2(float a, float b) {
    __half2 h = __floats2half2_rn(a, b);
    return *(uint32_t*)&h;
}
__device__ __forceinline__ uint32_t exp2_pack(float lo, float hi) {
    uint32_t w;
    asm("cvt.rn.f16x2.f32 %0, %1, %2;" : "=r"(w) : "f"(hi), "f"(lo));
    asm("ex2.approx.f16x2 %0, %0;" : "+r"(w));
    return w;
}
__device__ __forceinline__ uint32_t smem_u32(const void* p) {
    uint32_t a;
    asm("{ .reg .u64 t; cvta.to.shared.u64 t, %1; cvt.u32.u64 %0, t; }" : "=r"(a) : "l"(p));
    return a;
}
__device__ __forceinline__ void cp16(uint32_t dst, const void* src) {
    asm volatile("cp.async.cg.shared.global [%0], [%1], 16;" :: "r"(dst), "l"(src));
}
#define CP_COMMIT() asm volatile("cp.async.commit_group;" ::: "memory")
#define CP_WAIT0()  asm volatile("cp.async.wait_group 0;" ::: "memory")

__device__ __forceinline__ float4 ldcs4(const float4* p) {
    float4 v;
    asm volatile("ld.global.cs.v4.f32 {%0,%1,%2,%3}, [%4];"
                 : "=f"(v.x), "=f"(v.y), "=f"(v.z), "=f"(v.w) : "l"(p));
    return v;
}
__device__ __forceinline__ void stcs4(float4* p, float4 v) {
    asm volatile("st.global.cs.v4.f32 [%0], {%1,%2,%3,%4};"
                 :: "l"(p), "f"(v.x), "f"(v.y), "f"(v.z), "f"(v.w));
}

__device__ __forceinline__ void ldsm4(uint32_t* r, uint32_t addr) {
    asm volatile("ldmatrix.sync.aligned.m8n8.x4.shared.b16 {%0,%1,%2,%3}, [%4];"
                 : "=r"(r[0]), "=r"(r[1]), "=r"(r[2]), "=r"(r[3]) : "r"(addr));
}
__device__ __forceinline__ void ldsm4t(uint32_t* r, uint32_t addr) {
    asm volatile("ldmatrix.sync.aligned.m8n8.x4.trans.shared.b16 {%0,%1,%2,%3}, [%4];"
                 : "=r"(r[0]), "=r"(r[1]), "=r"(r[2]), "=r"(r[3]) : "r"(addr));
}
__device__ __forceinline__ void mma_f16(float* c, uint32_t a0, uint32_t a1, uint32_t a2,
                                        uint32_t a3, uint32_t b0, uint32_t b1) {
    asm volatile("mma.sync.aligned.m16n8k16.row.col.f32.f16.f16.f32 "
                 "{%0,%1,%2,%3}, {%4,%5,%6,%7}, {%8,%9}, {%0,%1,%2,%3};"
                 : "+f"(c[0]), "+f"(c[1]), "+f"(c[2]), "+f"(c[3])
                 : "r"(a0), "r"(a1), "r"(a2), "r"(a3), "r"(b0), "r"(b1));
}

// ---------------- prep: fp32 -> fp16 convert (K/V) + inv_map scatter-fill ----------
// inv_map is pre-set to -1 by cudaMemsetAsync before this kernel.
__global__ void convert_kernel(const float* __restrict__ xk, const float* __restrict__ xv,
                               const int* __restrict__ sel) {
    int i = blockIdx.x * blockDim.x + threadIdx.x;
    if (i < Bc * Sc) inv_map[sel[i]] = i;
    if (i < KN / 4) {
        float4 a = ((const float4*)xk)[i];
        *(uint2*)(k16g + 4 * (size_t)i) = make_uint2(h2(a.x, a.y), h2(a.z, a.w));
        float4 b = ((const float4*)xv)[i];
        *(uint2*)(v16g + 4 * (size_t)i) = make_uint2(h2(b.x, b.y), h2(b.z, b.w));
    }
}

// ---------------- fused: fp16 flash attention + KV write-out ----------------
__global__ __launch_bounds__(NTHREADS, 2)
void attn_mma_kernel(const float* __restrict__ xq, const float* __restrict__ kvb,
                     const float* __restrict__ xk, const float* __restrict__ xv,
                     float* __restrict__ out, float* __restrict__ kv_out) {
    const int tid = threadIdx.x;

    // ---- KV-writer CTAs (no smem use, no syncs; streaming ld/st keeps L2 for K/V) ----
    if (blockIdx.x >= QTILES) {
        const int widx = (blockIdx.x - QTILES) + 4 * (blockIdx.y + 32 * blockIdx.z);
        const int per = KV_ELEMS / 4 / WCTAS;            // 16384 float4
        const size_t base = (size_t)widx * per;
        const int per_slot = 2 * KVHc * Dc / 4;          // 512
        const int per_tok  = KVHc * Dc / 4;              // 256
        for (int j = tid; j < per; j += NTHREADS) {
            size_t i = base + j;
            int slot = (int)(i / per_slot);
            int rem  = (int)(i - (size_t)slot * per_slot);
            int t = inv_map[slot];
            float4 v;
            if (t < 0)               v = ldcs4((const float4*)kvb + i);
            else if (rem < per_tok)  v = ((const float4*)xk)[(size_t)t * per_tok + rem];
            else                     v = ((const float4*)xv)[(size_t)t * per_tok + rem - per_tok];
            stcs4((float4*)kv_out + i, v);
        }
        return;
    }

    // ---- attention CTAs ----
    extern __shared__ uint32_t smw[];
    const uint32_t sb = smem_u32(smw);

    const int lane = tid & 31;
    const int warp = tid >> 5;     // 0..3
    const int g    = lane >> 2;
    const int c    = lane & 3;

    const int qt  = (QTILES - 1) - blockIdx.x;    // longest CTAs first
    const int h   = blockIdx.y;
    const int b   = blockIdx.z;
    const int kvh = h >> 2;
    const int q0  = qt * BQ;
    const int wr0 = q0 + warp * 32;               // warp's first query row

    // ldmatrix per-lane base addresses (stage-0; add STAGEB for stage 1)
    const uint32_t qa0 = sb + (uint32_t)(warp * 32 + (lane & 15)) * ROWB + ((lane >> 4) & 1) * 16;
    const uint32_t qa1 = qa0 + 16 * ROWB;
    const uint32_t ka0 = sb + SM_S0 * 4
                       + (uint32_t)((lane & 7) + ((lane >> 4) & 1) * 8) * ROWB
                       + ((lane >> 3) & 1) * 16;
    const uint32_t va0 = sb + SM_S0 * 4 + 64 * ROWB
                       + (uint32_t)((lane & 7) + ((lane >> 3) & 1) * 8) * ROWB
                       + ((lane >> 4) & 1) * 16;

    const int niter = 2 * qt + 2;

    // staging: hoisted per-thread addressing (rows tid>>4 + 8k, chunk tid&15)
    const int sch = tid & 15, sr0 = tid >> 4;
    const uint32_t s_off = (uint32_t)sr0 * ROWB + sch * 16;
    const size_t  g_off = (size_t)sr0 * (KVHc * Dc) + sch * 8;

    // hoisted global K/V cursors (advance by BK tokens per issued stage)
    const __half* kg = k16g + ((size_t)(b * Sc) * KVHc + kvh) * Dc + g_off;
    const __half* vg = v16g + ((size_t)(b * Sc) * KVHc + kvh) * Dc + g_off;
    const size_t STEP = (size_t)BK * (KVHc * Dc);

    // ---- prologue: issue K/V stage 0 FIRST, then convert+stage Q under it ----
    {
        uint32_t kd = sb + SM_S0 * 4 + s_off;
#pragma unroll
        for (int k = 0; k < 8; ++k) {
            cp16(kd + k * (8 * ROWB), kg + (size_t)k * (8 * KVHc * Dc));
            cp16(kd + 64 * ROWB + k * (8 * ROWB), vg + (size_t)k * (8 * KVHc * Dc));
        }
        CP_COMMIT();
        kg += STEP; vg += STEP;

        const float* qb = xq + ((size_t)(b * Sc + q0) * Hc + h) * Dc;
        for (int idx = tid; idx < 128 * 32; idx += NTHREADS) {
            int c4 = idx & 31, row = idx >> 5;
            float4 v = *(const float4*)(qb + (size_t)row * (Hc * Dc) + c4 * 4);
            *(uint2*)(smw + SM_Qw + row * QKSTR + c4 * 2) =
                make_uint2(h2(v.x * SCALE2, v.y * SCALE2), h2(v.z * SCALE2, v.w * SCALE2));
        }
    }

    float o[2][16][4];
#pragma unroll
    for (int m = 0; m < 2; ++m)
#pragma unroll
        for (int n = 0; n < 16; ++n) { o[m][n][0] = o[m][n][1] = o[m][n][2] = o[m][n][3] = 0.0f; }
    float lacc[2][4] = {{0.f, 0.f, 0.f, 0.f}, {0.f, 0.f, 0.f, 0.f}};

    for (int it = 0; it < niter; ++it) {
        const int k0 = it * BK;

        CP_WAIT0();
        __syncthreads();

        if (it + 1 < niter) {
            const uint32_t sdst = sb + (((it + 1) & 1) ? SM_S1 : SM_S0) * 4 + s_off;
#pragma unroll
            for (int k = 0; k < 8; ++k) {
                cp16(sdst + k * (8 * ROWB), kg + (size_t)k * (8 * KVHc * Dc));
                cp16(sdst + 64 * ROWB + k * (8 * ROWB), vg + (size_t)k * (8 * KVHc * Dc));
            }
            CP_COMMIT();
            kg += STEP; vg += STEP;
        }

        if (k0 > wr0 + 31) continue;   // fully masked for this warp (warp-uniform)

        const uint32_t soff = (it & 1) ? (uint32_t)STAGEB : 0u;
        const uint32_t ka = ka0 + soff;
        const uint32_t va = va0 + soff;

        // ---- S = Q K^T : software-pipelined fragments ----
        float s[2][8][4];
#pragma unroll
        for (int m = 0; m < 2; ++m)
#pragma unroll
            for (int n = 0; n < 8; ++n) { s[m][n][0] = s[m][n][1] = s[m][n][2] = s[m][n][3] = 0.0f; }

        uint32_t kb[2][4], qx[2][4], qy[2][4];
        ldsm4(qx[0], qa0);
        ldsm4(qy[0], qa1);
        ldsm4(kb[0], ka);
#pragma unroll
        for (int ks = 0; ks < 8; ++ks) {
            uint32_t* x = qx[ks & 1];
            uint32_t* y = qy[ks & 1];
#pragma unroll
            for (int j = 0; j < 4; ++j) {
                if (j < 3)            ldsm4(kb[(j + 1) & 1], ka + (j + 1) * (16 * ROWB) + ks * 32);
                else if (ks < 7)      ldsm4(kb[0],           ka + (ks + 1) * 32);
                if (j == 1 && ks < 7) ldsm4(qx[(ks + 1) & 1], qa0 + (ks + 1) * 32);
                if (j == 2 && ks < 7) ldsm4(qy[(ks + 1) & 1], qa1 + (ks + 1) * 32);
                uint32_t* kc = kb[j & 1];
                mma_f16(s[0][2 * j],     x[0], x[1], x[2], x[3], kc[0], kc[1]);
                mma_f16(s[0][2 * j + 1], x[0], x[1], x[2], x[3], kc[2], kc[3]);
                mma_f16(s[1][2 * j],     y[0], y[1], y[2], y[3], kc[0], kc[1]);
                mma_f16(s[1][2 * j + 1], y[0], y[1], y[2], y[3], kc[2], kc[3]);
            }
        }

        // ---- softmax: packed half2 exp2 -> A fragments ----
        uint32_t pf[2][4][4];
        const bool domask = (k0 + 63 > wr0);   // warp-uniform
#pragma unroll
        for (int m = 0; m < 2; ++m) {
            const int qgA = wr0 + 16 * m + g;
            const int qgB = qgA + 8;
#pragma unroll
            for (int n = 0; n < 8; ++n) {
                float s0 = s[m][n][0], s1 = s[m][n][1], s2 = s[m][n][2], s3 = s[m][n][3];
                if (domask) {
                    int kg2 = k0 + n * 8 + 2 * c;
                    const float NINF = -__int_as_float(0x7f800000);
                    if (kg2 + 0 > qgA) s0 = NINF;
                    if (kg2 + 1 > qgA) s1 = NINF;
                    if (kg2 + 0 > qgB) s2 = NINF;
                    if (kg2 + 1 > qgB) s3 = NINF;
                }
                uint32_t w01 = exp2_pack(s0, s1);
                uint32_t w23 = exp2_pack(s2, s3);
                int ks = n >> 1;
                if (n & 1) { pf[m][ks][2] = w01; pf[m][ks][3] = w23; }
                else       { pf[m][ks][0] = w01; pf[m][ks][1] = w23; }
            }
        }

        // ---- O += P V ; l += P * ones : software-pipelined V fragments ----
        uint32_t vb[2][4];
        ldsm4t(vb[0], va);
#pragma unroll
        for (int ks = 0; ks < 4; ++ks) {
#pragma unroll
            for (int j = 0; j < 8; ++j) {
                if (j < 7)       ldsm4t(vb[(j + 1) & 1], va + ks * (16 * ROWB) + (j + 1) * 32);
                else if (ks < 3) ldsm4t(vb[0],           va + (ks + 1) * (16 * ROWB));
                if (j == 0) {
                    mma_f16(lacc[0], pf[0][ks][0], pf[0][ks][1], pf[0][ks][2], pf[0][ks][3], ONES2, ONES2);
                    mma_f16(lacc[1], pf[1][ks][0], pf[1][ks][1], pf[1][ks][2], pf[1][ks][3], ONES2, ONES2);
                }
                uint32_t* vc = vb[j & 1];
                mma_f16(o[0][2 * j],     pf[0][ks][0], pf[0][ks][1], pf[0][ks][2], pf[0][ks][3], vc[0], vc[1]);
                mma_f16(o[0][2 * j + 1], pf[0][ks][0], pf[0][ks][1], pf[0][ks][2], pf[0][ks][3], vc[2], vc[3]);
                mma_f16(o[1][2 * j],     pf[1][ks][0], pf[1][ks][1], pf[1][ks][2], pf[1][ks][3], vc[0], vc[1]);
                mma_f16(o[1][2 * j + 1], pf[1][ks][0], pf[1][ks][1], pf[1][ks][2], pf[1][ks][3], vc[2], vc[3]);
            }
        }
    }

    // ---- epilogue (no shuffles: ones-MMA left full row sums in lanes) ----
#pragma unroll
    for (int m = 0; m < 2; ++m) {
        const int qgA = wr0 + 16 * m + g;
        const int qgB = qgA + 8;
        float invA = 1.0f / lacc[m][0];
        float invB = 1.0f / lacc[m][2];
        float* obA = out + ((size_t)(b * Sc + qgA) * Hc + h) * Dc;
        float* obB = out + ((size_t)(b * Sc + qgB) * Hc + h) * Dc;
#pragma unroll
        for (int n = 0; n < 16; ++n) {
            int col = n * 8 + 2 * c;
            *(float2*)(obA + col) = make_float2(o[m][n][0] * invA, o[m][n][1] * invA);
            *(float2*)(obB + col) = make_float2(o[m][n][2] * invB, o[m][n][3] * invB);
        }
    }
}

// ---------------------------------------------------------------------------
extern "C" void kernel_launch(void* const* d_in, const int* in_sizes, int n_in,
                              void* d_out, int out_size) {
    const float* xq  = (const float*)d_in[0];
    const float* xk  = (const float*)d_in[1];
    const float* xv  = (const float*)d_in[2];
    const float* kvb = (const float*)d_in[3];
    const int*   sel = (const int*)d_in[4];

    float* out    = (float*)d_out;
    float* kv_out = out + OUT_ELEMS;

    // 0) inv_map = -1 via async memset (graph-capturable, no alloc)
    void* inv_ptr = nullptr;
    cudaGetSymbolAddress(&inv_ptr, inv_map);
    cudaMemsetAsync(inv_ptr, 0xFF, NUM_SLOTS * sizeof(int));

    // 1) convert K/V to fp16 + scatter-fill inverse map (init done by memset)
    convert_kernel<<<(KN / 4 + 255) / 256, 256>>>(xk, xv, sel);

    // 2) fused attention + KV write
    const int smem_bytes = SM_WORDS * 4;   // 104,448 B -> 2 CTAs/SM
    cudaFuncSetAttribute(attn_mma_kernel, cudaFuncAttributeMaxDynamicSharedMemorySize, smem_bytes);
    dim3 grid(QTILES + 4, Hc, Bc);   // (20, 32, 2): 1024 attn CTAs + 256 writer CTAs
    attn_mma_kernel<<<grid, NTHREADS, smem_bytes>>>(xq, kvb, xk, xv, out, kv_out);
}